// round 5
// baseline (speedup 1.0000x reference)
#include <cuda_runtime.h>
#include <cstdint>

// out[n,m,o] = sum_k sum_f x[n, idx[m,k], f] * iv[m,k] * W[k,f,o] + bias[o]
// N=16, M=65536, FIN=FOUT=32, K=7
static constexpr int N_ = 16, M_ = 65536, K_ = 7;
static constexpr int TILE_R = 128;

// Offsets relative to 1024-aligned A base
static constexpr int OFF_IDX = 16384;                 // 896 x i32  (3584 B)
static constexpr int OFF_IV  = 19968;                 // 896 x f32  (3584 B)
static constexpr int OFF_B   = 23552;                 // 7 x 64rows x 80B = 35840 B
static constexpr int B_KSTR  = 5120;                  // per-k B tile stride
static constexpr int SM_TOTAL = 23552 + 7 * B_KSTR + 1024;  // 60416 (incl. align slack)

__device__ __forceinline__ uint32_t smem_u32(const void* p) {
    uint32_t a;
    asm("{ .reg .u64 t; cvta.to.shared.u64 t, %1; cvt.u32.u64 %0, t; }" : "=r"(a) : "l"(p));
    return a;
}
// pack two f32 -> bf16x2 (first arg -> bits[15:0], second -> bits[31:16]), round-nearest
__device__ __forceinline__ uint32_t pack_bf16x2(float lo_half, float hi_half) {
    uint32_t r;
    asm("cvt.rn.bf16x2.f32 %0, %1, %2;" : "=r"(r) : "f"(hi_half), "f"(lo_half));
    return r;
}
// SW128 swizzle of a byte offset relative to a 1024-aligned tile base
__device__ __forceinline__ uint32_t swz(uint32_t b) { return b ^ ((b >> 3) & 0x70u); }

__device__ __forceinline__ void ldmA(uint32_t* r, uint32_t addr) {
    asm volatile("ldmatrix.sync.aligned.m8n8.x4.shared.b16 {%0,%1,%2,%3}, [%4];"
                 : "=r"(r[0]), "=r"(r[1]), "=r"(r[2]), "=r"(r[3]) : "r"(addr));
}
__device__ __forceinline__ void ldmBT(uint32_t* r, uint32_t addr) {
    asm volatile("ldmatrix.sync.aligned.m8n8.x4.trans.shared.b16 {%0,%1,%2,%3}, [%4];"
                 : "=r"(r[0]), "=r"(r[1]), "=r"(r[2]), "=r"(r[3]) : "r"(addr));
}
__device__ __forceinline__ void mma16816(float* c, const uint32_t* a, uint32_t b0, uint32_t b1) {
    asm volatile(
        "mma.sync.aligned.m16n8k16.row.col.f32.bf16.bf16.f32 "
        "{%0,%1,%2,%3}, {%4,%5,%6,%7}, {%8,%9}, {%0,%1,%2,%3};"
        : "+f"(c[0]), "+f"(c[1]), "+f"(c[2]), "+f"(c[3])
        : "r"(a[0]), "r"(a[1]), "r"(a[2]), "r"(a[3]), "r"(b0), "r"(b1));
}

__global__ void __launch_bounds__(128)
gfc_hmma_kernel(const float* __restrict__ x,
                const float* __restrict__ w,
                const float* __restrict__ bias,
                const int*   __restrict__ idxl,
                const float* __restrict__ ivv,
                float*       __restrict__ out)
{
    extern __shared__ char smem_raw[];
    const uint32_t sb = smem_u32(smem_raw);
    const uint32_t aA = (sb + 1023u) & ~1023u;      // 1024-aligned A tile base (SW128)

    const int tid = threadIdx.x;
    const int wid = tid >> 5;
    const int lan = tid & 31;
    const int m0  = blockIdx.x * TILE_R;
    const int n   = blockIdx.y;

    char* base = smem_raw + (aA - sb);
    int*   sIdx = (int*)  (base + OFF_IDX);
    float* sIv  = (float*)(base + OFF_IV);

    // --- stage idx / iv (contiguous) ---
    #pragma unroll
    for (int i = tid; i < TILE_R * K_; i += 128) {
        sIdx[i] = idxl[m0 * K_ + i];
        sIv[i]  = ivv [m0 * K_ + i];
    }

    // --- stage B tiles: per k, 64 K-rows (f=0..31 hi, 32..63 lo) x 32 cols bf16, row stride 80B ---
    for (int i = tid; i < K_ * 1024; i += 128) {
        const int k = i >> 10, rem = i & 1023, f = rem >> 5, o = rem & 31;
        const float v = w[(k << 10) + f * 32 + o];
        const uint32_t hp = pack_bf16x2(v, v);                  // rn bf16 in low half
        const uint16_t hb = (uint16_t)(hp & 0xFFFFu);
        const float    hf = __uint_as_float((uint32_t)hb << 16);
        const float    lf = v - hf;
        const uint16_t lb = (uint16_t)(pack_bf16x2(lf, lf) & 0xFFFFu);
        char* bt = base + OFF_B + k * B_KSTR;
        *(uint16_t*)(bt + f * 80 + o * 2)        = hb;
        *(uint16_t*)(bt + (32 + f) * 80 + o * 2) = lb;
    }
    __syncthreads();

    // accumulators: acc[mt][nt][4]  (mt: 16-row tiles, nt: 8-col tiles)
    float acc[2][4][4];
    #pragma unroll
    for (int mt = 0; mt < 2; ++mt)
        #pragma unroll
        for (int nt = 0; nt < 4; ++nt)
            #pragma unroll
            for (int e = 0; e < 4; ++e)
                acc[mt][nt][e] = 0.f;

    // gather mapping: lane = q*8 + r8 (q: 16B chunk / f-group, r8: row mod 8)
    const int q  = lan >> 3;
    const int r8 = lan & 7;
    const float4* x4 = reinterpret_cast<const float4*>(x);
    const int xb = n * (M_ * 8);

    for (int k = 0; k < K_; ++k) {
        // prefetch gather rows (overlaps other warps' MMA of k-1 across the barrier)
        float4 va[4], vb[4];
        float  sc[4];
        int    rw[4];
        #pragma unroll
        for (int rr = 0; rr < 4; ++rr) {
            const int r = rr * 32 + wid * 8 + r8;
            rw[rr] = r;
            const int src = sIdx[r * K_ + k];
            sc[rr] = sIv[r * K_ + k];
            const float4* p = x4 + xb + src * 8 + q * 2;
            va[rr] = __ldg(p);
            vb[rr] = __ldg(p + 1);
        }

        if (k) __syncthreads();   // all warps done reading A(k-1)

        // convert + split + transposed-by-K store: row = 128B: [hi f0..31 | lo f0..31]
        #pragma unroll
        for (int rr = 0; rr < 4; ++rr) {
            const float s = sc[rr];
            const float f0 = va[rr].x * s, f1 = va[rr].y * s, f2 = va[rr].z * s, f3 = va[rr].w * s;
            const float f4 = vb[rr].x * s, f5 = vb[rr].y * s, f6 = vb[rr].z * s, f7 = vb[rr].w * s;
            uint4 hi;
            hi.x = pack_bf16x2(f0, f1);
            hi.y = pack_bf16x2(f2, f3);
            hi.z = pack_bf16x2(f4, f5);
            hi.w = pack_bf16x2(f6, f7);
            uint4 lo;
            lo.x = pack_bf16x2(f0 - __uint_as_float(hi.x << 16),
                               f1 - __uint_as_float(hi.x & 0xFFFF0000u));
            lo.y = pack_bf16x2(f2 - __uint_as_float(hi.y << 16),
                               f3 - __uint_as_float(hi.y & 0xFFFF0000u));
            lo.z = pack_bf16x2(f4 - __uint_as_float(hi.z << 16),
                               f5 - __uint_as_float(hi.z & 0xFFFF0000u));
            lo.w = pack_bf16x2(f6 - __uint_as_float(hi.w << 16),
                               f7 - __uint_as_float(hi.w & 0xFFFF0000u));
            const uint32_t rowb = (uint32_t)(rw[rr] << 7);
            *(uint4*)(base + swz(rowb + (q << 4)))      = hi;   // cols [8q,8q+8) hi
            *(uint4*)(base + swz(rowb + 64 + (q << 4))) = lo;   // cols 32+[8q,8q+8) lo
        }
        __syncthreads();

        // warp GEMM: rows wid*32..+31, all 32 cols.
        // 3-term split: a_hi*w_hi + a_lo*w_hi + a_hi*w_lo  (lo*lo dropped, ~2^-18)
        const uint32_t bk = aA + OFF_B + k * B_KSTR;
        #pragma unroll
        for (int c = 0; c < 2; ++c) {          // K16 sub-chunk: f in [16c, 16c+16)
            const int arow = wid * 32 + (lan & 15);
            const uint32_t cbh = (uint32_t)(c * 32 + ((lan >> 4) << 4)); // hi bytes
            const uint32_t cbl = cbh + 64;                               // lo bytes
            uint32_t Ah[2][4], Al[2][4];
            ldmA(Ah[0], aA + swz((uint32_t)(arow << 7) + cbh));
            ldmA(Ah[1], aA + swz((uint32_t)((arow + 16) << 7) + cbh));
            ldmA(Al[0], aA + swz((uint32_t)(arow << 7) + cbl));
            ldmA(Al[1], aA + swz((uint32_t)((arow + 16) << 7) + cbl));

            const int krow_h = c * 16 + (lan & 7) + (((lan >> 3) & 1) << 3);
            const int krow_l = krow_h + 32;
            const int nc0    = (lan >> 4) << 3;
            uint32_t Bh[2][4], Bl[2][4];
            ldmBT(Bh[0], bk + krow_h * 80 + nc0 * 2);         // n 0..15
            ldmBT(Bh[1], bk + krow_h * 80 + (16 + nc0) * 2);  // n 16..31
            ldmBT(Bl[0], bk + krow_l * 80 + nc0 * 2);
            ldmBT(Bl[1], bk + krow_l * 80 + (16 + nc0) * 2);

            #pragma unroll
            for (int mt = 0; mt < 2; ++mt) {
                // a_hi * w_hi
                mma16816(acc[mt][0], Ah[mt], Bh[0][0], Bh[0][1]);
                mma16816(acc[mt][1], Ah[mt], Bh[0][2], Bh[0][3]);
                mma16816(acc[mt][2], Ah[mt], Bh[1][0], Bh[1][1]);
                mma16816(acc[mt][3], Ah[mt], Bh[1][2], Bh[1][3]);
                // a_lo * w_hi
                mma16816(acc[mt][0], Al[mt], Bh[0][0], Bh[0][1]);
                mma16816(acc[mt][1], Al[mt], Bh[0][2], Bh[0][3]);
                mma16816(acc[mt][2], Al[mt], Bh[1][0], Bh[1][1]);
                mma16816(acc[mt][3], Al[mt], Bh[1][2], Bh[1][3]);
                // a_hi * w_lo
                mma16816(acc[mt][0], Ah[mt], Bl[0][0], Bl[0][1]);
                mma16816(acc[mt][1], Ah[mt], Bl[0][2], Bl[0][3]);
                mma16816(acc[mt][2], Ah[mt], Bl[1][0], Bl[1][1]);
                mma16816(acc[mt][3], Ah[mt], Bl[1][2], Bl[1][3]);
            }
        }
    }

    // --- epilogue: fragment layout -> global f32 + bias ---
    const int quad = lan >> 2;           // 0..7 (row within 8)
    const int tq   = lan & 3;            // col pair
    float2 bv[4];
    const float2* b2 = reinterpret_cast<const float2*>(bias);
    #pragma unroll
    for (int nt = 0; nt < 4; ++nt) bv[nt] = __ldg(b2 + nt * 4 + tq);

    #pragma unroll
    for (int mt = 0; mt < 2; ++mt) {
        const int r0 = m0 + wid * 32 + mt * 16 + quad;
        #pragma unroll
        for (int nt = 0; nt < 4; ++nt) {
            float2 v0, v1;
            v0.x = acc[mt][nt][0] + bv[nt].x;
            v0.y = acc[mt][nt][1] + bv[nt].y;
            v1.x = acc[mt][nt][2] + bv[nt].x;
            v1.y = acc[mt][nt][3] + bv[nt].y;
            const int c = nt * 8 + tq * 2;
            *reinterpret_cast<float2*>(out + ((size_t)(n * M_ + r0)) * 32 + c)       = v0;
            *reinterpret_cast<float2*>(out + ((size_t)(n * M_ + r0 + 8)) * 32 + c)   = v1;
        }
    }
}

extern "C" void kernel_launch(void* const* d_in, const int* in_sizes, int n_in,
                              void* d_out, int out_size)
{
    const float* x    = (const float*)d_in[0];   // (16, 65536, 32) f32
    const float* wgt  = (const float*)d_in[1];   // (7, 32, 32) f32
    const float* bias = (const float*)d_in[2];   // (32,) f32
    const int*   idx  = (const int*)  d_in[3];   // (65536*7,) i32
    const float* iv   = (const float*)d_in[4];   // (65536, 7) f32
    float* out = (float*)d_out;                  // (16, 65536, 32) f32

    cudaFuncSetAttribute(gfc_hmma_kernel,
                         cudaFuncAttributeMaxDynamicSharedMemorySize, SM_TOTAL);
    dim3 grid(M_ / TILE_R, N_, 1);               // (512, 16)
    gfc_hmma_kernel<<<grid, 128, SM_TOTAL>>>(x, wgt, bias, idx, iv, out);
}